// round 16
// baseline (speedup 1.0000x reference)
#include <cuda_runtime.h>
#include <cuda_fp16.h>

#define NN 50000
#define FIN 256
#define NHEADS 4
#define HIDD 32
#define HD 128            // NHEADS*HIDD
#define CC 16
#define EE 1600000
#define EPAD (EE + NN)    // edges + self loops
#define CSRMAX (EPAD + NN * 8)
#define NB1 ((NN + 1023) / 1024)
#define NEGBIG -1e30f
#define E4 (EE / 4)

// ------------------------- scratch (static device globals) -------------------------
__device__ __align__(16) __half g_xw1h[(NN + 1) * HD];
__device__ __align__(16) float g_asrc1[(NN + 1) * NHEADS];
__device__ __align__(16) float g_adst1[NN * NHEADS];
__device__ __align__(16) __half g_h1h[NN * HD];
__device__ __align__(16) __half g_h2h[(NN + 1) * CC];
__device__ __align__(16) float g_asrc2[NN + 1];
__device__ __align__(16) float g_adst2[NN];
__device__ __align__(16) unsigned long long g_w1p[16 * 128 * 4];
__device__ __align__(16) uint2 g_w2p[512];
__device__ __align__(16) float g_vs[HD];
__device__ __align__(16) float g_vd[HD];
__device__ int g_csrc[CSRMAX];
__device__ int g_rank[EE];       // per-edge rank within its destination (from k_prep)
__device__ int g_deg[NN];        // zero-init at load; re-zeroed by k_scatter tail each run
__device__ int g_rowptr[NN + 1];
__device__ int g_bsum[64];

__device__ __forceinline__ float leaky(float x) { return x > 0.f ? x : 0.2f * x; }

// ------------------------- graph prep -------------------------
__device__ __forceinline__ bool detect64(const int* ei) {
    return (ei[1] == 0) && (ei[3] == 0) && (ei[5] == 0) && (ei[7] == 0);
}

// histogram + rank recording (the only atomic pass); g_deg is zero on entry
// (module-load init on first call, scatter-tail re-zero on every call).
__global__ void k_prep(const int* __restrict__ ei) {
    bool is64 = detect64(ei);
    int t = blockIdx.x * blockDim.x + threadIdx.x;
    if (t >= E4) return;
    int d0, d1, d2, d3;
    if (is64) {
        int4 a = *(const int4*)&ei[2 * EE + 8 * t];
        int4 b = *(const int4*)&ei[2 * EE + 8 * t + 4];
        d0 = a.x; d1 = a.z; d2 = b.x; d3 = b.z;
    } else {
        int4 a = *(const int4*)&ei[EE + 4 * t];
        d0 = a.x; d1 = a.y; d2 = a.z; d3 = a.w;
    }
    int4 r;
    r.x = atomicAdd(&g_deg[d0], 1);
    r.y = atomicAdd(&g_deg[d1], 1);
    r.z = atomicAdd(&g_deg[d2], 1);
    r.w = atomicAdd(&g_deg[d3], 1);
    *(int4*)&g_rank[4 * t] = r;
}

// block-wise exclusive scan of PADDED degrees (deg+1 self loop, rounded to 8)
__global__ __launch_bounds__(1024) void k_scan1() {
    int t = threadIdx.x, b = blockIdx.x;
    int i = b * 1024 + t;
    int val = (i < NN) ? ((g_deg[i] + 1 + 7) & ~7) : 0;
    int lane = t & 31, wid = t >> 5;
    int x = val;
#pragma unroll
    for (int off = 1; off < 32; off <<= 1) {
        int y = __shfl_up_sync(0xffffffffu, x, off);
        if (lane >= off) x += y;
    }
    __shared__ int wsum[32];
    if (lane == 31) wsum[wid] = x;
    __syncthreads();
    if (wid == 0) {
        int w = wsum[lane];
#pragma unroll
        for (int off = 1; off < 32; off <<= 1) {
            int y = __shfl_up_sync(0xffffffffu, w, off);
            if (lane >= off) w += y;
        }
        wsum[lane] = w;
    }
    __syncthreads();
    int incl = x + (wid > 0 ? wsum[wid - 1] : 0);
    if (i < NN) g_rowptr[i] = incl - val;
    if (t == 1023) g_bsum[b] = incl;
}

__global__ __launch_bounds__(256) void k_scan3() {
    __shared__ int s[64];
    int t = threadIdx.x;
    int chunk = blockIdx.x >> 2;
    if (t < 64) s[t] = (t < chunk) ? g_bsum[t] : 0;
    __syncthreads();
    if (t < 32) {
        int v = s[t] + s[t + 32];
#pragma unroll
        for (int off = 16; off; off >>= 1)
            v += __shfl_down_sync(0xffffffffu, v, off);
        if (t == 0) s[0] = v;
    }
    __syncthreads();
    int pref = s[0];
    int i = blockIdx.x * 256 + t;
    if (i < NN) {
        int v = g_rowptr[i] + pref;
        g_rowptr[i] = v;
        if (i == NN - 1) g_rowptr[NN] = v + ((g_deg[i] + 1 + 7) & ~7);
    }
}

// atomic-free scatter via precomputed ranks + fused node tail (self loop, pads,
// sentinels) + g_deg re-zero for the next graph replay.
__global__ void k_scatter(const int* __restrict__ ei) {
    bool is64 = detect64(ei);
    int t = blockIdx.x * blockDim.x + threadIdx.x;
    if (t < E4) {
        int s0, s1, s2, s3, d0, d1, d2, d3;
        if (is64) {
            int4 a = *(const int4*)&ei[8 * t];
            int4 b = *(const int4*)&ei[8 * t + 4];
            s0 = a.x; s1 = a.z; s2 = b.x; s3 = b.z;
            int4 c = *(const int4*)&ei[2 * EE + 8 * t];
            int4 e = *(const int4*)&ei[2 * EE + 8 * t + 4];
            d0 = c.x; d1 = c.z; d2 = e.x; d3 = e.z;
        } else {
            int4 a = *(const int4*)&ei[4 * t];
            s0 = a.x; s1 = a.y; s2 = a.z; s3 = a.w;
            int4 c = *(const int4*)&ei[EE + 4 * t];
            d0 = c.x; d1 = c.y; d2 = c.z; d3 = c.w;
        }
        int4 r = *(const int4*)&g_rank[4 * t];
        g_csrc[g_rowptr[d0] + r.x] = s0;
        g_csrc[g_rowptr[d1] + r.y] = s1;
        g_csrc[g_rowptr[d2] + r.z] = s2;
        g_csrc[g_rowptr[d3] + r.w] = s3;
        return;
    }
    int j = t - E4;
    if (j < NN) {
        int deg = g_deg[j];
        g_deg[j] = 0;                                          // reset for next replay
        int base = g_rowptr[j] + deg;
        int end = g_rowptr[j + 1];
        g_csrc[base] = j;                                      // self loop
        for (int e = base + 1; e < end; e++) g_csrc[e] = NN;   // sentinel pads
    } else {
        int k = j - NN;
        if (k < 32) *(uint2*)&g_xw1h[NN * HD + k * 4] = make_uint2(0, 0);
        else if (k < 36) *(uint2*)&g_h2h[NN * CC + (k - 32) * 4] = make_uint2(0, 0);
        else if (k < 40) g_asrc1[NN * NHEADS + (k - 36)] = NEGBIG;
        else if (k == 40) g_asrc2[NN] = NEGBIG;
    }
}

// ------------------------- weight preprocessing -------------------------
__global__ void k_w1pack(const float* __restrict__ W1) {
    int tid = blockIdx.x * blockDim.x + threadIdx.x;   // 8192
    int kt = tid >> 9;
    int c = (tid >> 2) & 127;
    int m = tid & 3;
    int kb = kt * 16 + m * 2;
    float v0 = W1[kb * HD + c];
    float v1 = W1[(kb + 1) * HD + c];
    float v8 = W1[(kb + 8) * HD + c];
    float v9 = W1[(kb + 9) * HD + c];
    __half2 lo = __floats2half2_rn(v0, v1);
    __half2 hi = __floats2half2_rn(v8, v9);
    unsigned long long u = ((unsigned long long)*(unsigned*)&hi << 32) | *(unsigned*)&lo;
    g_w1p[tid] = u;
}

__global__ void k_w2v(const float* __restrict__ W2,
                      const float* __restrict__ as2,
                      const float* __restrict__ ad2) {
    int t = threadIdx.x;   // 0..511
    if (t < HD) {
        float s = 0.f, d = 0.f;
#pragma unroll
        for (int c = 0; c < CC; c++) {
            float w = W2[t * CC + c];
            s = fmaf(w, as2[c], s);
            d = fmaf(w, ad2[c], d);
        }
        g_vs[t] = s;
        g_vd[t] = d;
    }
    int kt = t >> 6, tile = (t >> 5) & 1, lane = t & 31;
    int n = tile * 8 + (lane >> 2);
    int m = lane & 3;
    int k0 = kt * 16 + m * 2;
    __half2 lo = __floats2half2_rn(W2[k0 * CC + n], W2[(k0 + 1) * CC + n]);
    __half2 hi = __floats2half2_rn(W2[(k0 + 8) * CC + n], W2[(k0 + 9) * CC + n]);
    g_w2p[t] = make_uint2(*(unsigned*)&lo, *(unsigned*)&hi);
}

// ------------------------- GEMM1: HMMA, B from L2, fused attn epilogue ------------
#define AS_STRIDE 40
__global__ __launch_bounds__(256, 3) void k_gemm1(const float* __restrict__ x,
                                                  const float* __restrict__ att_src,
                                                  const float* __restrict__ att_dst) {
    __shared__ __align__(16) __half As[64][AS_STRIDE];
    const int m0 = blockIdx.x * 64;
    const int tid = threadIdx.x;
    const int w = tid >> 5, lane = tid & 31;
    const int q = lane >> 2, m = lane & 3;
    const int mrow = (w & 3) * 16;
    const int ncol = (w >> 2) * 64;

    float acc[8][4];
#pragma unroll
    for (int i = 0; i < 8; i++)
#pragma unroll
        for (int c = 0; c < 4; c++) acc[i][c] = 0.f;

    const uint2* Bp = (const uint2*)g_w1p;
    const int bbase = ((ncol + q) << 2) + m;
    const int arow = tid >> 3, akg = tid & 7;
    const unsigned aaddr = (unsigned)__cvta_generic_to_shared(
        &As[mrow + (lane & 15)][(lane >> 4) * 8]);

    for (int k0 = 0; k0 < FIN; k0 += 32) {
#pragma unroll
        for (int rr = 0; rr < 2; rr++) {
            int r = arow + rr * 32;
            int row = m0 + r;
            float4 v = make_float4(0.f, 0.f, 0.f, 0.f);
            if (row < NN) v = *(const float4*)&x[row * FIN + k0 + akg * 4];
            __half2 h01 = __floats2half2_rn(v.x, v.y);
            __half2 h23 = __floats2half2_rn(v.z, v.w);
            *(uint2*)&As[r][akg * 4] = make_uint2(*(unsigned*)&h01, *(unsigned*)&h23);
        }
        __syncthreads();
        int kt0 = k0 >> 4;
#pragma unroll
        for (int kk = 0; kk < 2; kk++) {
            unsigned ra0, ra1, ra2, ra3;
            asm volatile("ldmatrix.sync.aligned.m8n8.x4.shared.b16 {%0,%1,%2,%3}, [%4];"
                         : "=r"(ra0), "=r"(ra1), "=r"(ra2), "=r"(ra3)
                         : "r"(aaddr + kk * 32));
            const uint2* bp = Bp + (kt0 + kk) * 512 + bbase;
            uint2 bf[8];
#pragma unroll
            for (int i = 0; i < 8; i++) bf[i] = bp[i << 5];
#pragma unroll
            for (int i = 0; i < 8; i++) {
                asm("mma.sync.aligned.m16n8k16.row.col.f32.f16.f16.f32 "
                    "{%0,%1,%2,%3}, {%4,%5,%6,%7}, {%8,%9}, {%0,%1,%2,%3};"
                    : "+f"(acc[i][0]), "+f"(acc[i][1]), "+f"(acc[i][2]), "+f"(acc[i][3])
                    : "r"(ra0), "r"(ra1), "r"(ra2), "r"(ra3), "r"(bf[i].x), "r"(bf[i].y));
            }
        }
        __syncthreads();
    }

    int row0 = m0 + mrow + q, row1 = row0 + 8;
    bool ok0 = row0 < NN, ok1 = row1 < NN;
    float ps[2][2] = {{0.f, 0.f}, {0.f, 0.f}};
    float pd[2][2] = {{0.f, 0.f}, {0.f, 0.f}};
#pragma unroll
    for (int i = 0; i < 8; i++) {
        int c = ncol + i * 8 + m * 2;
        float s0 = att_src[c], s1 = att_src[c + 1];
        float d0 = att_dst[c], d1 = att_dst[c + 1];
        int hh = i >> 2;
        if (ok0) {
            __half2 hv = __floats2half2_rn(acc[i][0], acc[i][1]);
            *(unsigned*)&g_xw1h[row0 * HD + c] = *(unsigned*)&hv;
        }
        if (ok1) {
            __half2 hv = __floats2half2_rn(acc[i][2], acc[i][3]);
            *(unsigned*)&g_xw1h[row1 * HD + c] = *(unsigned*)&hv;
        }
        ps[0][hh] += acc[i][0] * s0 + acc[i][1] * s1;
        pd[0][hh] += acc[i][0] * d0 + acc[i][1] * d1;
        ps[1][hh] += acc[i][2] * s0 + acc[i][3] * s1;
        pd[1][hh] += acc[i][2] * d0 + acc[i][3] * d1;
    }
#pragma unroll
    for (int off = 1; off < 4; off <<= 1) {
#pragma unroll
        for (int r = 0; r < 2; r++)
#pragma unroll
            for (int hh = 0; hh < 2; hh++) {
                ps[r][hh] += __shfl_xor_sync(0xffffffffu, ps[r][hh], off);
                pd[r][hh] += __shfl_xor_sync(0xffffffffu, pd[r][hh], off);
            }
    }
    if (m == 0) {
        int h0 = (w >> 2) * 2;
        if (ok0) {
            g_asrc1[row0 * NHEADS + h0] = ps[0][0];
            g_asrc1[row0 * NHEADS + h0 + 1] = ps[0][1];
            g_adst1[row0 * NHEADS + h0] = pd[0][0];
            g_adst1[row0 * NHEADS + h0 + 1] = pd[0][1];
        }
        if (ok1) {
            g_asrc1[row1 * NHEADS + h0] = ps[1][0];
            g_asrc1[row1 * NHEADS + h0 + 1] = ps[1][1];
            g_adst1[row1 * NHEADS + h0] = pd[1][0];
            g_adst1[row1 * NHEADS + h0 + 1] = pd[1][1];
        }
    }
}

// ------------------------- layer-1 aggregation (2 warps per node) ----------------
__device__ __forceinline__ void h4_to_f4(uint2 u, float& a, float& b, float& c, float& d) {
    float2 lo = __half22float2(*(__half2*)&u.x);
    float2 hi = __half22float2(*(__half2*)&u.y);
    a = lo.x; b = lo.y; c = hi.x; d = hi.y;
}

// block = 256 threads = 8 warps = 4 nodes (2 warps/node, alternating 8-edge chunks)
__global__ __launch_bounds__(256) void k_agg1(const float* __restrict__ b1) {
    __shared__ float com[4][5][32];
    int t = blockIdx.x * 256 + threadIdx.x;
    int gw = t >> 5;
    int n = gw >> 1;
    int half = gw & 1;
    int lane = t & 31;
    int nl = threadIdx.x >> 6;

    const int h = lane >> 3;
    const int sel = lane & 7;
    const int grpBase = lane & 24;
    const float adst = g_adst1[n * NHEADS + h];
    int p1 = g_rowptr[n + 1];
    int p = g_rowptr[n] + half * 8;

    float ax = 0.f, ay = 0.f, az = 0.f, aw = 0.f, den = 0.f;
    int4 ia = __ldg((const int4*)&g_csrc[p]);
    int4 ib = __ldg((const int4*)&g_csrc[p + 4]);
    for (; p < p1; p += 16) {
        int4 na = __ldg((const int4*)&g_csrc[p + 16]);
        int4 nb = __ldg((const int4*)&g_csrc[p + 20]);
        int s[8] = {ia.x, ia.y, ia.z, ia.w, ib.x, ib.y, ib.z, ib.w};
        float amy = __ldg(&g_asrc1[s[sel] * NHEADS + h]);
        uint2 u[8];
#pragma unroll
        for (int i = 0; i < 8; i++) u[i] = __ldg((const uint2*)&g_xw1h[s[i] * HD + lane * 4]);
        float emy = __expf(leaky(amy + adst));
        den += emy;
#pragma unroll
        for (int i = 0; i < 8; i++) {
            float e = __shfl_sync(0xffffffffu, emy, grpBase | i);
            float vx, vy, vz, vw;
            h4_to_f4(u[i], vx, vy, vz, vw);
            ax = fmaf(e, vx, ax); ay = fmaf(e, vy, ay);
            az = fmaf(e, vz, az); aw = fmaf(e, vw, aw);
        }
        ia = na; ib = nb;
    }
    den += __shfl_xor_sync(0xffffffffu, den, 1);
    den += __shfl_xor_sync(0xffffffffu, den, 2);
    den += __shfl_xor_sync(0xffffffffu, den, 4);

    if (half) {
        com[nl][0][lane] = ax;
        com[nl][1][lane] = ay;
        com[nl][2][lane] = az;
        com[nl][3][lane] = aw;
        com[nl][4][lane] = den;
    }
    __syncthreads();
    if (half) return;

    ax += com[nl][0][lane];
    ay += com[nl][1][lane];
    az += com[nl][2][lane];
    aw += com[nl][3][lane];
    den += com[nl][4][lane];

    float inv = __fdividef(1.f, den);
    float4 bv = *(const float4*)&b1[lane * 4];
    float4 hv;
    hv.x = fmaxf(fmaf(ax, inv, bv.x), 0.f);
    hv.y = fmaxf(fmaf(ay, inv, bv.y), 0.f);
    hv.z = fmaxf(fmaf(az, inv, bv.z), 0.f);
    hv.w = fmaxf(fmaf(aw, inv, bv.w), 0.f);

    {
        __half2 h01 = __floats2half2_rn(hv.x, hv.y);
        __half2 h23 = __floats2half2_rn(hv.z, hv.w);
        *(uint2*)&g_h1h[n * HD + lane * 4] = make_uint2(*(unsigned*)&h01, *(unsigned*)&h23);
    }

    float4 vsv = *(const float4*)&g_vs[lane * 4];
    float4 vdv = *(const float4*)&g_vd[lane * 4];
    float asum = hv.x * vsv.x + hv.y * vsv.y + hv.z * vsv.z + hv.w * vsv.w;
    float dsum = hv.x * vdv.x + hv.y * vdv.y + hv.z * vdv.z + hv.w * vdv.w;
#pragma unroll
    for (int off = 16; off; off >>= 1) {
        asum += __shfl_down_sync(0xffffffffu, asum, off);
        dsum += __shfl_down_sync(0xffffffffu, dsum, off);
    }
    if (lane == 0) {
        g_asrc2[n] = asum;
        g_adst2[n] = dsum;
    }
}

// ------------------------- GEMM2: h2 = h1 @ W2 (HMMA, 64 rows/block) --------------
#define A2_STRIDE 136
__global__ __launch_bounds__(128) void k_gemm2() {
    __shared__ __align__(16) __half Ah[64][A2_STRIDE];
    const int m0 = blockIdx.x * 64;
    const int tid = threadIdx.x;
    const int w = tid >> 5, lane = tid & 31;
    const int q = lane >> 2, m = lane & 3;
    const int mrow = w * 16;

    {
        int row = tid >> 1;
        int cb = (tid & 1) * 8;
        bool ok = (m0 + row) < NN;
        const uint4* src = (const uint4*)&g_h1h[(m0 + row) * HD];
#pragma unroll
        for (int j = 0; j < 8; j++) {
            uint4 v = ok ? src[cb + j] : make_uint4(0, 0, 0, 0);
            *(uint4*)&Ah[row][(cb + j) * 8] = v;
        }
    }
    __syncthreads();

    float acc[2][4];
#pragma unroll
    for (int tl = 0; tl < 2; tl++)
#pragma unroll
        for (int c = 0; c < 4; c++) acc[tl][c] = 0.f;

    const unsigned aaddr = (unsigned)__cvta_generic_to_shared(
        &Ah[mrow + (lane & 15)][(lane >> 4) * 8]);
#pragma unroll
    for (int kt = 0; kt < 8; kt++) {
        unsigned ra0, ra1, ra2, ra3;
        asm volatile("ldmatrix.sync.aligned.m8n8.x4.shared.b16 {%0,%1,%2,%3}, [%4];"
                     : "=r"(ra0), "=r"(ra1), "=r"(ra2), "=r"(ra3)
                     : "r"(aaddr + kt * 32));
#pragma unroll
        for (int tl = 0; tl < 2; tl++) {
            uint2 bf = g_w2p[kt * 64 + tl * 32 + lane];
            asm("mma.sync.aligned.m16n8k16.row.col.f32.f16.f16.f32 "
                "{%0,%1,%2,%3}, {%4,%5,%6,%7}, {%8,%9}, {%0,%1,%2,%3};"
                : "+f"(acc[tl][0]), "+f"(acc[tl][1]), "+f"(acc[tl][2]), "+f"(acc[tl][3])
                : "r"(ra0), "r"(ra1), "r"(ra2), "r"(ra3), "r"(bf.x), "r"(bf.y));
        }
    }

    int r0 = m0 + mrow + q, r1 = r0 + 8;
#pragma unroll
    for (int tl = 0; tl < 2; tl++) {
        int c = tl * 8 + 2 * m;
        if (r0 < NN) {
            __half2 hv = __floats2half2_rn(acc[tl][0], acc[tl][1]);
            *(unsigned*)&g_h2h[r0 * CC + c] = *(unsigned*)&hv;
        }
        if (r1 < NN) {
            __half2 hv = __floats2half2_rn(acc[tl][2], acc[tl][3]);
            *(unsigned*)&g_h2h[r1 * CC + c] = *(unsigned*)&hv;
        }
    }
}

// ------------------------- layer-2 aggregation + fused bias/log_softmax ----------
__global__ void k_agg2(const float* __restrict__ b2, float* __restrict__ out) {
    int t = blockIdx.x * blockDim.x + threadIdx.x;
    int n = t >> 2;
    bool valid = n < NN;
    if (n >= NN) n = NN - 1;
    int j = t & 3;
    const int grpBase = (t & 31) & ~3;
    const unsigned gmask = 0xFu << grpBase;
    const float adst = g_adst2[n];
    int p = g_rowptr[n], p1 = g_rowptr[n + 1];
    float ax = 0.f, ay = 0.f, az = 0.f, aw = 0.f, den = 0.f;
    int4 ia = __ldg((const int4*)&g_csrc[p]);
    int4 ib = __ldg((const int4*)&g_csrc[p + 4]);
    for (; p < p1; p += 8) {
        int4 na = __ldg((const int4*)&g_csrc[p + 8]);
        int4 nb = __ldg((const int4*)&g_csrc[p + 12]);
        int s[8] = {ia.x, ia.y, ia.z, ia.w, ib.x, ib.y, ib.z, ib.w};
        float aa = __ldg(&g_asrc2[s[j]]);
        float ab = __ldg(&g_asrc2[s[j + 4]]);
        uint2 u[8];
#pragma unroll
        for (int i = 0; i < 8; i++) u[i] = __ldg((const uint2*)&g_h2h[s[i] * CC + j * 4]);
        float ea = __expf(leaky(aa + adst));
        float eb = __expf(leaky(ab + adst));
        den += ea + eb;
#pragma unroll
        for (int i = 0; i < 8; i++) {
            float e = __shfl_sync(gmask, (i < 4) ? ea : eb, grpBase | (i & 3));
            float vx, vy, vz, vw;
            h4_to_f4(u[i], vx, vy, vz, vw);
            ax = fmaf(e, vx, ax); ay = fmaf(e, vy, ay);
            az = fmaf(e, vz, az); aw = fmaf(e, vw, aw);
        }
        ia = na; ib = nb;
    }
    den += __shfl_xor_sync(gmask, den, 1);
    den += __shfl_xor_sync(gmask, den, 2);
    float inv = __fdividef(1.f, den);
    float4 bb = *(const float4*)&b2[j * 4];
    float4 o = make_float4(fmaf(ax, inv, bb.x), fmaf(ay, inv, bb.y),
                           fmaf(az, inv, bb.z), fmaf(aw, inv, bb.w));
    float mx = fmaxf(fmaxf(o.x, o.y), fmaxf(o.z, o.w));
    mx = fmaxf(mx, __shfl_xor_sync(0xffffffffu, mx, 1));
    mx = fmaxf(mx, __shfl_xor_sync(0xffffffffu, mx, 2));
    float s = __expf(o.x - mx) + __expf(o.y - mx) + __expf(o.z - mx) + __expf(o.w - mx);
    s += __shfl_xor_sync(0xffffffffu, s, 1);
    s += __shfl_xor_sync(0xffffffffu, s, 2);
    float l = mx + logf(s);
    o.x -= l; o.y -= l; o.z -= l; o.w -= l;
    if (valid) *(float4*)&out[n * CC + j * 4] = o;
}

// ------------------------- launch -------------------------
extern "C" void kernel_launch(void* const* d_in, const int* in_sizes, int n_in,
                              void* d_out, int out_size) {
    const float* x   = (const float*)d_in[0];
    const int*   ei  = (const int*)d_in[1];
    const float* W1  = (const float*)d_in[2];
    const float* as1 = (const float*)d_in[3];
    const float* ad1 = (const float*)d_in[4];
    const float* b1  = (const float*)d_in[5];
    const float* W2  = (const float*)d_in[6];
    const float* as2 = (const float*)d_in[7];
    const float* ad2 = (const float*)d_in[8];
    const float* b2  = (const float*)d_in[9];
    float* out = (float*)d_out;

    static cudaStream_t s1 = nullptr;
    static cudaEvent_t evFork = nullptr, evJoin = nullptr;
    if (!s1) {
        cudaStreamCreate(&s1);
        cudaEventCreateWithFlags(&evFork, cudaEventDisableTiming);
        cudaEventCreateWithFlags(&evJoin, cudaEventDisableTiming);
    }

    // no memset: g_deg is zero-initialized at module load and re-zeroed by the
    // k_scatter tail each invocation.
    cudaEventRecord(evFork, 0);

    // s1: weight prep + GEMM1 (enqueued FIRST — insertion order matters for concurrency)
    cudaStreamWaitEvent(s1, evFork, 0);
    k_w1pack<<<32, 256, 0, s1>>>(W1);
    k_w2v<<<1, 512, 0, s1>>>(W2, as2, ad2);
    k_gemm1<<<(NN + 63) / 64, 256, 0, s1>>>(x, as1, ad1);
    cudaEventRecord(evJoin, s1);

    // main: graph prep
    k_prep<<<(E4 + 255) / 256, 256>>>(ei);
    k_scan1<<<NB1, 1024>>>();
    k_scan3<<<(NN + 255) / 256, 256>>>();
    k_scatter<<<(E4 + NN + 64 + 255) / 256, 256>>>(ei);

    // join, then aggregation chain
    cudaStreamWaitEvent(0, evJoin, 0);
    k_agg1<<<(NN * 64) / 256, 256>>>(b1);
    k_gemm2<<<(NN + 63) / 64, 128>>>();
    k_agg2<<<(NN * 4 + 255) / 256, 256>>>(b2, out);
}

// round 17
// speedup vs baseline: 1.0197x; 1.0197x over previous
#include <cuda_runtime.h>
#include <cuda_fp16.h>

#define NN 50000
#define FIN 256
#define NHEADS 4
#define HIDD 32
#define HD 128            // NHEADS*HIDD
#define CC 16
#define EE 1600000
#define EPAD (EE + NN)    // edges + self loops
#define CSRMAX (EPAD + NN * 8)
#define NB1 ((NN + 1023) / 1024)
#define NEGBIG -1e30f
#define E4 (EE / 4)

// ------------------------- scratch (static device globals) -------------------------
__device__ __align__(16) __half g_xw1h[(NN + 1) * HD];
__device__ __align__(16) float g_asrc1[(NN + 1) * NHEADS];
__device__ __align__(16) float g_adst1[NN * NHEADS];
__device__ __align__(16) __half g_h1h[NN * HD];
__device__ __align__(16) __half g_h2h[(NN + 1) * CC];
__device__ __align__(16) float g_asrc2[NN + 1];
__device__ __align__(16) float g_adst2[NN];
__device__ __align__(16) unsigned long long g_w1p[16 * 128 * 4];
__device__ __align__(16) uint2 g_w2p[512];
__device__ __align__(16) float g_vs[HD];
__device__ __align__(16) float g_vd[HD];
__device__ int g_csrc[CSRMAX];
__device__ int g_rank[EE];       // per-edge rank within its destination (from k_prep)
__device__ int g_deg[NN];
__device__ int g_rowptr[NN + 1];
__device__ int g_bsum[64];

__device__ __forceinline__ float leaky(float x) { return x > 0.f ? x : 0.2f * x; }

// ------------------------- graph prep -------------------------
__device__ __forceinline__ bool detect64(const int* ei) {
    return (ei[1] == 0) && (ei[3] == 0) && (ei[5] == 0) && (ei[7] == 0);
}

// histogram + rank recording (the only atomic pass)
__global__ void k_prep(const int* __restrict__ ei) {
    bool is64 = detect64(ei);
    int t = blockIdx.x * blockDim.x + threadIdx.x;
    if (t >= E4) return;
    int d0, d1, d2, d3;
    if (is64) {
        int4 a = __ldg((const int4*)&ei[2 * EE + 8 * t]);
        int4 b = __ldg((const int4*)&ei[2 * EE + 8 * t + 4]);
        d0 = a.x; d1 = a.z; d2 = b.x; d3 = b.z;
    } else {
        int4 a = __ldg((const int4*)&ei[EE + 4 * t]);
        d0 = a.x; d1 = a.y; d2 = a.z; d3 = a.w;
    }
    int4 r;
    r.x = atomicAdd(&g_deg[d0], 1);
    r.y = atomicAdd(&g_deg[d1], 1);
    r.z = atomicAdd(&g_deg[d2], 1);
    r.w = atomicAdd(&g_deg[d3], 1);
    *(int4*)&g_rank[4 * t] = r;
}

// block-wise exclusive scan of PADDED degrees (deg+1 self loop, rounded to 8)
__global__ __launch_bounds__(1024) void k_scan1() {
    int t = threadIdx.x, b = blockIdx.x;
    int i = b * 1024 + t;
    int val = (i < NN) ? ((g_deg[i] + 1 + 7) & ~7) : 0;
    int lane = t & 31, wid = t >> 5;
    int x = val;
#pragma unroll
    for (int off = 1; off < 32; off <<= 1) {
        int y = __shfl_up_sync(0xffffffffu, x, off);
        if (lane >= off) x += y;
    }
    __shared__ int wsum[32];
    if (lane == 31) wsum[wid] = x;
    __syncthreads();
    if (wid == 0) {
        int w = wsum[lane];
#pragma unroll
        for (int off = 1; off < 32; off <<= 1) {
            int y = __shfl_up_sync(0xffffffffu, w, off);
            if (lane >= off) w += y;
        }
        wsum[lane] = w;
    }
    __syncthreads();
    int incl = x + (wid > 0 ? wsum[wid - 1] : 0);
    if (i < NN) g_rowptr[i] = incl - val;
    if (t == 1023) g_bsum[b] = incl;
}

__global__ __launch_bounds__(256) void k_scan3() {
    __shared__ int s[64];
    int t = threadIdx.x;
    int chunk = blockIdx.x >> 2;
    if (t < 64) s[t] = (t < chunk) ? g_bsum[t] : 0;
    __syncthreads();
    if (t < 32) {
        int v = s[t] + s[t + 32];
#pragma unroll
        for (int off = 16; off; off >>= 1)
            v += __shfl_down_sync(0xffffffffu, v, off);
        if (t == 0) s[0] = v;
    }
    __syncthreads();
    int pref = s[0];
    int i = blockIdx.x * 256 + t;
    if (i < NN) {
        int v = g_rowptr[i] + pref;
        g_rowptr[i] = v;
        if (i == NN - 1) g_rowptr[NN] = v + ((g_deg[i] + 1 + 7) & ~7);
    }
}

// atomic-free scatter via precomputed ranks + fused node tail (self loop, pads, sentinels)
__global__ void k_scatter(const int* __restrict__ ei) {
    bool is64 = detect64(ei);
    int t = blockIdx.x * blockDim.x + threadIdx.x;
    if (t < E4) {
        int s0, s1, s2, s3, d0, d1, d2, d3;
        if (is64) {
            int4 a = __ldg((const int4*)&ei[8 * t]);
            int4 b = __ldg((const int4*)&ei[8 * t + 4]);
            s0 = a.x; s1 = a.z; s2 = b.x; s3 = b.z;
            int4 c = __ldg((const int4*)&ei[2 * EE + 8 * t]);
            int4 e = __ldg((const int4*)&ei[2 * EE + 8 * t + 4]);
            d0 = c.x; d1 = c.z; d2 = e.x; d3 = e.z;
        } else {
            int4 a = __ldg((const int4*)&ei[4 * t]);
            s0 = a.x; s1 = a.y; s2 = a.z; s3 = a.w;
            int4 c = __ldg((const int4*)&ei[EE + 4 * t]);
            d0 = c.x; d1 = c.y; d2 = c.z; d3 = c.w;
        }
        int4 r = __ldg((const int4*)&g_rank[4 * t]);
        g_csrc[g_rowptr[d0] + r.x] = s0;
        g_csrc[g_rowptr[d1] + r.y] = s1;
        g_csrc[g_rowptr[d2] + r.z] = s2;
        g_csrc[g_rowptr[d3] + r.w] = s3;
        return;
    }
    int j = t - E4;
    if (j < NN) {
        int base = g_rowptr[j] + g_deg[j];
        int end = g_rowptr[j + 1];
        g_csrc[base] = j;                                      // self loop
        for (int e = base + 1; e < end; e++) g_csrc[e] = NN;   // sentinel pads
    } else {
        int k = j - NN;
        if (k < 32) *(uint2*)&g_xw1h[NN * HD + k * 4] = make_uint2(0, 0);
        else if (k < 36) *(uint2*)&g_h2h[NN * CC + (k - 32) * 4] = make_uint2(0, 0);
        else if (k < 40) g_asrc1[NN * NHEADS + (k - 36)] = NEGBIG;
        else if (k == 40) g_asrc2[NN] = NEGBIG;
    }
}

// ------------------------- weight preprocessing -------------------------
__global__ void k_w1pack(const float* __restrict__ W1) {
    int tid = blockIdx.x * blockDim.x + threadIdx.x;   // 8192
    int kt = tid >> 9;
    int c = (tid >> 2) & 127;
    int m = tid & 3;
    int kb = kt * 16 + m * 2;
    float v0 = W1[kb * HD + c];
    float v1 = W1[(kb + 1) * HD + c];
    float v8 = W1[(kb + 8) * HD + c];
    float v9 = W1[(kb + 9) * HD + c];
    __half2 lo = __floats2half2_rn(v0, v1);
    __half2 hi = __floats2half2_rn(v8, v9);
    unsigned long long u = ((unsigned long long)*(unsigned*)&hi << 32) | *(unsigned*)&lo;
    g_w1p[tid] = u;
}

__global__ void k_w2v(const float* __restrict__ W2,
                      const float* __restrict__ as2,
                      const float* __restrict__ ad2) {
    int t = threadIdx.x;   // 0..511
    if (t < HD) {
        float s = 0.f, d = 0.f;
#pragma unroll
        for (int c = 0; c < CC; c++) {
            float w = W2[t * CC + c];
            s = fmaf(w, as2[c], s);
            d = fmaf(w, ad2[c], d);
        }
        g_vs[t] = s;
        g_vd[t] = d;
    }
    int kt = t >> 6, tile = (t >> 5) & 1, lane = t & 31;
    int n = tile * 8 + (lane >> 2);
    int m = lane & 3;
    int k0 = kt * 16 + m * 2;
    __half2 lo = __floats2half2_rn(W2[k0 * CC + n], W2[(k0 + 1) * CC + n]);
    __half2 hi = __floats2half2_rn(W2[(k0 + 8) * CC + n], W2[(k0 + 9) * CC + n]);
    g_w2p[t] = make_uint2(*(unsigned*)&lo, *(unsigned*)&hi);
}

// ------------------------- GEMM1: HMMA, B from L2, fused attn epilogue ------------
#define AS_STRIDE 40
__global__ __launch_bounds__(256, 3) void k_gemm1(const float* __restrict__ x,
                                                  const float* __restrict__ att_src,
                                                  const float* __restrict__ att_dst) {
    __shared__ __align__(16) __half As[64][AS_STRIDE];
    const int m0 = blockIdx.x * 64;
    const int tid = threadIdx.x;
    const int w = tid >> 5, lane = tid & 31;
    const int q = lane >> 2, m = lane & 3;
    const int mrow = (w & 3) * 16;
    const int ncol = (w >> 2) * 64;

    float acc[8][4];
#pragma unroll
    for (int i = 0; i < 8; i++)
#pragma unroll
        for (int c = 0; c < 4; c++) acc[i][c] = 0.f;

    const uint2* Bp = (const uint2*)g_w1p;
    const int bbase = ((ncol + q) << 2) + m;
    const int arow = tid >> 3, akg = tid & 7;
    const unsigned aaddr = (unsigned)__cvta_generic_to_shared(
        &As[mrow + (lane & 15)][(lane >> 4) * 8]);

    for (int k0 = 0; k0 < FIN; k0 += 32) {
#pragma unroll
        for (int rr = 0; rr < 2; rr++) {
            int r = arow + rr * 32;
            int row = m0 + r;
            float4 v = make_float4(0.f, 0.f, 0.f, 0.f);
            if (row < NN) v = *(const float4*)&x[row * FIN + k0 + akg * 4];
            __half2 h01 = __floats2half2_rn(v.x, v.y);
            __half2 h23 = __floats2half2_rn(v.z, v.w);
            *(uint2*)&As[r][akg * 4] = make_uint2(*(unsigned*)&h01, *(unsigned*)&h23);
        }
        __syncthreads();
        int kt0 = k0 >> 4;
#pragma unroll
        for (int kk = 0; kk < 2; kk++) {
            unsigned ra0, ra1, ra2, ra3;
            asm volatile("ldmatrix.sync.aligned.m8n8.x4.shared.b16 {%0,%1,%2,%3}, [%4];"
                         : "=r"(ra0), "=r"(ra1), "=r"(ra2), "=r"(ra3)
                         : "r"(aaddr + kk * 32));
            const uint2* bp = Bp + (kt0 + kk) * 512 + bbase;
            uint2 bf[8];
#pragma unroll
            for (int i = 0; i < 8; i++) bf[i] = bp[i << 5];
#pragma unroll
            for (int i = 0; i < 8; i++) {
                asm("mma.sync.aligned.m16n8k16.row.col.f32.f16.f16.f32 "
                    "{%0,%1,%2,%3}, {%4,%5,%6,%7}, {%8,%9}, {%0,%1,%2,%3};"
                    : "+f"(acc[i][0]), "+f"(acc[i][1]), "+f"(acc[i][2]), "+f"(acc[i][3])
                    : "r"(ra0), "r"(ra1), "r"(ra2), "r"(ra3), "r"(bf[i].x), "r"(bf[i].y));
            }
        }
        __syncthreads();
    }

    int row0 = m0 + mrow + q, row1 = row0 + 8;
    bool ok0 = row0 < NN, ok1 = row1 < NN;
    float ps[2][2] = {{0.f, 0.f}, {0.f, 0.f}};
    float pd[2][2] = {{0.f, 0.f}, {0.f, 0.f}};
#pragma unroll
    for (int i = 0; i < 8; i++) {
        int c = ncol + i * 8 + m * 2;
        float s0 = att_src[c], s1 = att_src[c + 1];
        float d0 = att_dst[c], d1 = att_dst[c + 1];
        int hh = i >> 2;
        if (ok0) {
            __half2 hv = __floats2half2_rn(acc[i][0], acc[i][1]);
            *(unsigned*)&g_xw1h[row0 * HD + c] = *(unsigned*)&hv;
        }
        if (ok1) {
            __half2 hv = __floats2half2_rn(acc[i][2], acc[i][3]);
            *(unsigned*)&g_xw1h[row1 * HD + c] = *(unsigned*)&hv;
        }
        ps[0][hh] += acc[i][0] * s0 + acc[i][1] * s1;
        pd[0][hh] += acc[i][0] * d0 + acc[i][1] * d1;
        ps[1][hh] += acc[i][2] * s0 + acc[i][3] * s1;
        pd[1][hh] += acc[i][2] * d0 + acc[i][3] * d1;
    }
#pragma unroll
    for (int off = 1; off < 4; off <<= 1) {
#pragma unroll
        for (int r = 0; r < 2; r++)
#pragma unroll
            for (int hh = 0; hh < 2; hh++) {
                ps[r][hh] += __shfl_xor_sync(0xffffffffu, ps[r][hh], off);
                pd[r][hh] += __shfl_xor_sync(0xffffffffu, pd[r][hh], off);
            }
    }
    if (m == 0) {
        int h0 = (w >> 2) * 2;
        if (ok0) {
            g_asrc1[row0 * NHEADS + h0] = ps[0][0];
            g_asrc1[row0 * NHEADS + h0 + 1] = ps[0][1];
            g_adst1[row0 * NHEADS + h0] = pd[0][0];
            g_adst1[row0 * NHEADS + h0 + 1] = pd[0][1];
        }
        if (ok1) {
            g_asrc1[row1 * NHEADS + h0] = ps[1][0];
            g_asrc1[row1 * NHEADS + h0 + 1] = ps[1][1];
            g_adst1[row1 * NHEADS + h0] = pd[1][0];
            g_adst1[row1 * NHEADS + h0 + 1] = pd[1][1];
        }
    }
}

// ------------------------- layer-1 aggregation (2 warps per node) ----------------
__device__ __forceinline__ void h4_to_f4(uint2 u, float& a, float& b, float& c, float& d) {
    float2 lo = __half22float2(*(__half2*)&u.x);
    float2 hi = __half22float2(*(__half2*)&u.y);
    a = lo.x; b = lo.y; c = hi.x; d = hi.y;
}

// block = 256 threads = 8 warps = 4 nodes (2 warps/node, alternating 8-edge chunks)
__global__ __launch_bounds__(256) void k_agg1(const float* __restrict__ b1) {
    __shared__ float com[4][5][32];
    int t = blockIdx.x * 256 + threadIdx.x;
    int gw = t >> 5;
    int n = gw >> 1;
    int half = gw & 1;
    int lane = t & 31;
    int nl = threadIdx.x >> 6;

    const int h = lane >> 3;
    const int sel = lane & 7;
    const int grpBase = lane & 24;
    const float adst = g_adst1[n * NHEADS + h];
    int p1 = g_rowptr[n + 1];
    int p = g_rowptr[n] + half * 8;

    float ax = 0.f, ay = 0.f, az = 0.f, aw = 0.f, den = 0.f;
    int4 ia = __ldg((const int4*)&g_csrc[p]);
    int4 ib = __ldg((const int4*)&g_csrc[p + 4]);
    for (; p < p1; p += 16) {
        int4 na = __ldg((const int4*)&g_csrc[p + 16]);
        int4 nb = __ldg((const int4*)&g_csrc[p + 20]);
        int s[8] = {ia.x, ia.y, ia.z, ia.w, ib.x, ib.y, ib.z, ib.w};
        float amy = __ldg(&g_asrc1[s[sel] * NHEADS + h]);
        uint2 u[8];
#pragma unroll
        for (int i = 0; i < 8; i++) u[i] = __ldg((const uint2*)&g_xw1h[s[i] * HD + lane * 4]);
        float emy = __expf(leaky(amy + adst));
        den += emy;
#pragma unroll
        for (int i = 0; i < 8; i++) {
            float e = __shfl_sync(0xffffffffu, emy, grpBase | i);
            float vx, vy, vz, vw;
            h4_to_f4(u[i], vx, vy, vz, vw);
            ax = fmaf(e, vx, ax); ay = fmaf(e, vy, ay);
            az = fmaf(e, vz, az); aw = fmaf(e, vw, aw);
        }
        ia = na; ib = nb;
    }
    den += __shfl_xor_sync(0xffffffffu, den, 1);
    den += __shfl_xor_sync(0xffffffffu, den, 2);
    den += __shfl_xor_sync(0xffffffffu, den, 4);

    if (half) {
        com[nl][0][lane] = ax;
        com[nl][1][lane] = ay;
        com[nl][2][lane] = az;
        com[nl][3][lane] = aw;
        com[nl][4][lane] = den;
    }
    __syncthreads();
    if (half) return;

    ax += com[nl][0][lane];
    ay += com[nl][1][lane];
    az += com[nl][2][lane];
    aw += com[nl][3][lane];
    den += com[nl][4][lane];

    float inv = __fdividef(1.f, den);
    float4 bv = *(const float4*)&b1[lane * 4];
    float4 hv;
    hv.x = fmaxf(fmaf(ax, inv, bv.x), 0.f);
    hv.y = fmaxf(fmaf(ay, inv, bv.y), 0.f);
    hv.z = fmaxf(fmaf(az, inv, bv.z), 0.f);
    hv.w = fmaxf(fmaf(aw, inv, bv.w), 0.f);

    {
        __half2 h01 = __floats2half2_rn(hv.x, hv.y);
        __half2 h23 = __floats2half2_rn(hv.z, hv.w);
        *(uint2*)&g_h1h[n * HD + lane * 4] = make_uint2(*(unsigned*)&h01, *(unsigned*)&h23);
    }

    float4 vsv = *(const float4*)&g_vs[lane * 4];
    float4 vdv = *(const float4*)&g_vd[lane * 4];
    float asum = hv.x * vsv.x + hv.y * vsv.y + hv.z * vsv.z + hv.w * vsv.w;
    float dsum = hv.x * vdv.x + hv.y * vdv.y + hv.z * vdv.z + hv.w * vdv.w;
#pragma unroll
    for (int off = 16; off; off >>= 1) {
        asum += __shfl_down_sync(0xffffffffu, asum, off);
        dsum += __shfl_down_sync(0xffffffffu, dsum, off);
    }
    if (lane == 0) {
        g_asrc2[n] = asum;
        g_adst2[n] = dsum;
    }
}

// ------------------------- GEMM2: h2 = h1 @ W2 (HMMA, 64 rows/block) --------------
#define A2_STRIDE 136
__global__ __launch_bounds__(128) void k_gemm2() {
    __shared__ __align__(16) __half Ah[64][A2_STRIDE];
    const int m0 = blockIdx.x * 64;
    const int tid = threadIdx.x;
    const int w = tid >> 5, lane = tid & 31;
    const int q = lane >> 2, m = lane & 3;
    const int mrow = w * 16;

    {
        int row = tid >> 1;
        int cb = (tid & 1) * 8;
        bool ok = (m0 + row) < NN;
        const uint4* src = (const uint4*)&g_h1h[(m0 + row) * HD];
#pragma unroll
        for (int j = 0; j < 8; j++) {
            uint4 v = ok ? src[cb + j] : make_uint4(0, 0, 0, 0);
            *(uint4*)&Ah[row][(cb + j) * 8] = v;
        }
    }
    __syncthreads();

    float acc[2][4];
#pragma unroll
    for (int tl = 0; tl < 2; tl++)
#pragma unroll
        for (int c = 0; c < 4; c++) acc[tl][c] = 0.f;

    const unsigned aaddr = (unsigned)__cvta_generic_to_shared(
        &Ah[mrow + (lane & 15)][(lane >> 4) * 8]);
#pragma unroll
    for (int kt = 0; kt < 8; kt++) {
        unsigned ra0, ra1, ra2, ra3;
        asm volatile("ldmatrix.sync.aligned.m8n8.x4.shared.b16 {%0,%1,%2,%3}, [%4];"
                     : "=r"(ra0), "=r"(ra1), "=r"(ra2), "=r"(ra3)
                     : "r"(aaddr + kt * 32));
#pragma unroll
        for (int tl = 0; tl < 2; tl++) {
            uint2 bf = g_w2p[kt * 64 + tl * 32 + lane];
            asm("mma.sync.aligned.m16n8k16.row.col.f32.f16.f16.f32 "
                "{%0,%1,%2,%3}, {%4,%5,%6,%7}, {%8,%9}, {%0,%1,%2,%3};"
                : "+f"(acc[tl][0]), "+f"(acc[tl][1]), "+f"(acc[tl][2]), "+f"(acc[tl][3])
                : "r"(ra0), "r"(ra1), "r"(ra2), "r"(ra3), "r"(bf.x), "r"(bf.y));
        }
    }

    int r0 = m0 + mrow + q, r1 = r0 + 8;
#pragma unroll
    for (int tl = 0; tl < 2; tl++) {
        int c = tl * 8 + 2 * m;
        if (r0 < NN) {
            __half2 hv = __floats2half2_rn(acc[tl][0], acc[tl][1]);
            *(unsigned*)&g_h2h[r0 * CC + c] = *(unsigned*)&hv;
        }
        if (r1 < NN) {
            __half2 hv = __floats2half2_rn(acc[tl][2], acc[tl][3]);
            *(unsigned*)&g_h2h[r1 * CC + c] = *(unsigned*)&hv;
        }
    }
}

// ------------------------- layer-2 aggregation + fused bias/log_softmax ----------
__global__ void k_agg2(const float* __restrict__ b2, float* __restrict__ out) {
    int t = blockIdx.x * blockDim.x + threadIdx.x;
    int n = t >> 2;
    bool valid = n < NN;
    if (n >= NN) n = NN - 1;
    int j = t & 3;
    const int grpBase = (t & 31) & ~3;
    const unsigned gmask = 0xFu << grpBase;
    const float adst = g_adst2[n];
    int p = g_rowptr[n], p1 = g_rowptr[n + 1];
    float ax = 0.f, ay = 0.f, az = 0.f, aw = 0.f, den = 0.f;
    int4 ia = __ldg((const int4*)&g_csrc[p]);
    int4 ib = __ldg((const int4*)&g_csrc[p + 4]);
    for (; p < p1; p += 8) {
        int4 na = __ldg((const int4*)&g_csrc[p + 8]);
        int4 nb = __ldg((const int4*)&g_csrc[p + 12]);
        int s[8] = {ia.x, ia.y, ia.z, ia.w, ib.x, ib.y, ib.z, ib.w};
        float aa = __ldg(&g_asrc2[s[j]]);
        float ab = __ldg(&g_asrc2[s[j + 4]]);
        uint2 u[8];
#pragma unroll
        for (int i = 0; i < 8; i++) u[i] = __ldg((const uint2*)&g_h2h[s[i] * CC + j * 4]);
        float ea = __expf(leaky(aa + adst));
        float eb = __expf(leaky(ab + adst));
        den += ea + eb;
#pragma unroll
        for (int i = 0; i < 8; i++) {
            float e = __shfl_sync(gmask, (i < 4) ? ea : eb, grpBase | (i & 3));
            float vx, vy, vz, vw;
            h4_to_f4(u[i], vx, vy, vz, vw);
            ax = fmaf(e, vx, ax); ay = fmaf(e, vy, ay);
            az = fmaf(e, vz, az); aw = fmaf(e, vw, aw);
        }
        ia = na; ib = nb;
    }
    den += __shfl_xor_sync(gmask, den, 1);
    den += __shfl_xor_sync(gmask, den, 2);
    float inv = __fdividef(1.f, den);
    float4 bb = *(const float4*)&b2[j * 4];
    float4 o = make_float4(fmaf(ax, inv, bb.x), fmaf(ay, inv, bb.y),
                           fmaf(az, inv, bb.z), fmaf(aw, inv, bb.w));
    float mx = fmaxf(fmaxf(o.x, o.y), fmaxf(o.z, o.w));
    mx = fmaxf(mx, __shfl_xor_sync(0xffffffffu, mx, 1));
    mx = fmaxf(mx, __shfl_xor_sync(0xffffffffu, mx, 2));
    float s = __expf(o.x - mx) + __expf(o.y - mx) + __expf(o.z - mx) + __expf(o.w - mx);
    s += __shfl_xor_sync(0xffffffffu, s, 1);
    s += __shfl_xor_sync(0xffffffffu, s, 2);
    float l = mx + logf(s);
    o.x -= l; o.y -= l; o.z -= l; o.w -= l;
    if (valid) *(float4*)&out[n * CC + j * 4] = o;
}

// ------------------------- launch -------------------------
extern "C" void kernel_launch(void* const* d_in, const int* in_sizes, int n_in,
                              void* d_out, int out_size) {
    const float* x   = (const float*)d_in[0];
    const int*   ei  = (const int*)d_in[1];
    const float* W1  = (const float*)d_in[2];
    const float* as1 = (const float*)d_in[3];
    const float* ad1 = (const float*)d_in[4];
    const float* b1  = (const float*)d_in[5];
    const float* W2  = (const float*)d_in[6];
    const float* as2 = (const float*)d_in[7];
    const float* ad2 = (const float*)d_in[8];
    const float* b2  = (const float*)d_in[9];
    float* out = (float*)d_out;

    static cudaStream_t s1 = nullptr;
    static cudaEvent_t evFork = nullptr, evJoin = nullptr;
    static void* degPtr = nullptr;
    if (!s1) {
        cudaStreamCreate(&s1);
        cudaEventCreateWithFlags(&evFork, cudaEventDisableTiming);
        cudaEventCreateWithFlags(&evJoin, cudaEventDisableTiming);
        cudaGetSymbolAddress(&degPtr, g_deg);
    }

    cudaMemsetAsync(degPtr, 0, NN * sizeof(int));
    cudaEventRecord(evFork, 0);

    // s1: weight prep + GEMM1 (enqueued FIRST — insertion order matters for concurrency)
    cudaStreamWaitEvent(s1, evFork, 0);
    k_w1pack<<<32, 256, 0, s1>>>(W1);
    k_w2v<<<1, 512, 0, s1>>>(W2, as2, ad2);
    k_gemm1<<<(NN + 63) / 64, 256, 0, s1>>>(x, as1, ad1);
    cudaEventRecord(evJoin, s1);

    // main: graph prep
    k_prep<<<(E4 + 255) / 256, 256>>>(ei);
    k_scan1<<<NB1, 1024>>>();
    k_scan3<<<(NN + 255) / 256, 256>>>();
    k_scatter<<<(E4 + NN + 64 + 255) / 256, 256>>>(ei);

    // join, then aggregation chain
    cudaStreamWaitEvent(0, evJoin, 0);
    k_agg1<<<(NN * 64) / 256, 256>>>(b1);
    k_gemm2<<<(NN + 63) / 64, 128>>>();
    k_agg2<<<(NN * 4 + 255) / 256, 256>>>(b2, out);
}